// round 15
// baseline (speedup 1.0000x reference)
#include <cuda_runtime.h>
#include <cuda_bf16.h>
#include <cstdint>

#define NN 100000
#define EE 1600000
#define HH 8
#define CH 64
#define HC 512
#define GG 64
#define OUTC 10
#define NEG 0.2f
#define NB 98   // ceil(NN/1024)

// ---------------- scratch (device globals; no runtime allocation) ----------
// NOTE: only referenced from device code (host-side use binds the host shadow).
__device__ __nv_bfloat16 g_h16[(size_t)NN * HC];   // h features bf16 (agg gather src)
__device__ __nv_bfloat16 g_a16[(size_t)NN * HC];   // x1 bf16 (GEMM A), then x2 bf16
__device__ __nv_bfloat16 g_whi[HC * HC];           // W2^T hi (n-major, k fast)
__device__ __nv_bfloat16 g_wlo[HC * HC];           // W2^T lo residual
__device__ float g_als[NN * HH];
__device__ float g_ald[NN * HH];
__device__ int   g_deg[NN];
__device__ int   g_cnt[NN];
__device__ int   g_rowptr[NN + 1];
__device__ int   g_csrc[EE];
__device__ float g_pool[GG * HC];
__device__ float g_pcnt[GG];
__device__ int   g_bsum[NB];
__device__ int   g_boff[NB];

__device__ __forceinline__ float lrelu(float x) { return x > 0.f ? x : NEG * x; }
__device__ __forceinline__ float elu1(float x)  { return x > 0.f ? x : expm1f(x); }

__device__ __forceinline__ uint32_t smem_u32(const void* p) {
    uint32_t a;
    asm("{ .reg .u64 t; cvta.to.shared.u64 t, %1; cvt.u32.u64 %0, t; }" : "=r"(a) : "l"(p));
    return a;
}

__device__ __forceinline__ float4 ld_bf16x4(const __nv_bfloat16* p) {
    uint2 q = *(const uint2*)p;
    __nv_bfloat162 a = *reinterpret_cast<__nv_bfloat162*>(&q.x);
    __nv_bfloat162 b = *reinterpret_cast<__nv_bfloat162*>(&q.y);
    float2 fa = __bfloat1622float2(a), fb = __bfloat1622float2(b);
    return make_float4(fa.x, fa.y, fb.x, fb.y);
}
__device__ __forceinline__ void st_bf16x4(__nv_bfloat16* p, float4 v) {
    __nv_bfloat162 p0 = __float22bfloat162_rn(make_float2(v.x, v.y));
    __nv_bfloat162 p1 = __float22bfloat162_rn(make_float2(v.z, v.w));
    uint2 pk;
    pk.x = *reinterpret_cast<uint32_t*>(&p0);
    pk.y = *reinterpret_cast<uint32_t*>(&p1);
    *reinterpret_cast<uint2*>(p) = pk;
}
// 8 bf16 -> 8 floats
__device__ __forceinline__ void cvt8(uint4 q, float* f) {
    __nv_bfloat162 b0 = *reinterpret_cast<__nv_bfloat162*>(&q.x);
    __nv_bfloat162 b1 = *reinterpret_cast<__nv_bfloat162*>(&q.y);
    __nv_bfloat162 b2 = *reinterpret_cast<__nv_bfloat162*>(&q.z);
    __nv_bfloat162 b3 = *reinterpret_cast<__nv_bfloat162*>(&q.w);
    float2 f0 = __bfloat1622float2(b0), f1 = __bfloat1622float2(b1);
    float2 f2 = __bfloat1622float2(b2), f3 = __bfloat1622float2(b3);
    f[0] = f0.x; f[1] = f0.y; f[2] = f1.x; f[3] = f1.y;
    f[4] = f2.x; f[5] = f2.y; f[6] = f3.x; f[7] = f3.y;
}

// ---------------- init: zero accumulators --------------------------------
__global__ void init_kernel() {
    int i = blockIdx.x * blockDim.x + threadIdx.x;
    if (i < NN) { g_deg[i] = 0; g_cnt[i] = 0; }
    if (i < GG * HC) g_pool[i] = 0.f;
    if (i < GG) g_pcnt[i] = 0.f;
}

// ---------------- CSR build ------------------------------------------------
__global__ void count_kernel(const int* __restrict__ ei) {
    int e = blockIdx.x * blockDim.x + threadIdx.x;
    if (e >= EE) return;
    atomicAdd(&g_deg[ei[EE + e]], 1);   // dst
}

__global__ void scan1_kernel() {
    __shared__ int sh[1024];
    int tid = threadIdx.x;
    int i = blockIdx.x * 1024 + tid;
    int v = (i < NN) ? g_deg[i] : 0;
    sh[tid] = v;
    __syncthreads();
    for (int off = 1; off < 1024; off <<= 1) {
        int t = (tid >= off) ? sh[tid - off] : 0;
        __syncthreads();
        sh[tid] += t;
        __syncthreads();
    }
    if (i < NN) g_rowptr[i] = sh[tid] - v;
    if (tid == 1023) g_bsum[blockIdx.x] = sh[1023];
}

__global__ void scan2_kernel() {      // one block, parallel scan over NB
    __shared__ int sh[128];
    int tid = threadIdx.x;
    int v = (tid < NB) ? g_bsum[tid] : 0;
    sh[tid] = v;
    __syncthreads();
    for (int off = 1; off < 128; off <<= 1) {
        int t = (tid >= off) ? sh[tid - off] : 0;
        __syncthreads();
        sh[tid] += t;
        __syncthreads();
    }
    if (tid < NB) g_boff[tid] = sh[tid] - v;   // exclusive
}

__global__ void scan3_kernel() {
    int i = blockIdx.x * blockDim.x + threadIdx.x;
    if (i < NN) g_rowptr[i] += g_boff[i >> 10];
    if (i == 0) g_rowptr[NN] = EE;
}

__global__ void scatter_kernel(const int* __restrict__ ei) {
    int e = blockIdx.x * blockDim.x + threadIdx.x;
    if (e >= EE) return;
    int s = ei[e];
    int d = ei[EE + e];
    int pos = g_rowptr[d] + atomicAdd(&g_cnt[d], 1);
    g_csrc[pos] = s;
}

// ---------------- W2 split: hi/lo bf16, transposed (n-major, k fast) -------
__global__ void wsplit_kernel(const float* __restrict__ W2) {
    int idx = blockIdx.x * blockDim.x + threadIdx.x;   // 512*512
    int n = idx >> 9, k = idx & 511;
    float w = W2[k * HC + n];
    __nv_bfloat16 hi = __float2bfloat16(w);
    float lo = w - __bfloat162float(hi);
    g_whi[n * HC + k] = hi;
    g_wlo[n * HC + k] = __float2bfloat16(lo);
}

// ---------------- layer-1 projection (K=3) + attention logits -------------
// logits computed from exact fp32 register values; h1 stored bf16 only.
__global__ void proj1_al_kernel(const float* __restrict__ x,
                                const float* __restrict__ W1,
                                const float* __restrict__ a_s,
                                const float* __restrict__ a_d) {
    int n = blockIdx.x;
    int tid = threadIdx.x;
    float x0 = x[n * 3 + 0], x1 = x[n * 3 + 1], x2 = x[n * 3 + 2];
    int c4 = tid * 4;
    float4 w0 = *(const float4*)(W1 + 0 * HC + c4);
    float4 w1 = *(const float4*)(W1 + 1 * HC + c4);
    float4 w2 = *(const float4*)(W1 + 2 * HC + c4);
    float4 h;
    h.x = x0 * w0.x + x1 * w1.x + x2 * w2.x;
    h.y = x0 * w0.y + x1 * w1.y + x2 * w2.y;
    h.z = x0 * w0.z + x1 * w1.z + x2 * w2.z;
    h.w = x0 * w0.w + x1 * w1.w + x2 * w2.w;
    st_bf16x4(g_h16 + (size_t)n * HC + c4, h);

    int head = tid >> 4;
    int cc = (tid & 15) * 4;
    float4 as4 = *(const float4*)(a_s + head * CH + cc);
    float4 ad4 = *(const float4*)(a_d + head * CH + cc);
    float ps = h.x * as4.x + h.y * as4.y + h.z * as4.z + h.w * as4.w;
    float pd = h.x * ad4.x + h.y * ad4.y + h.z * ad4.z + h.w * ad4.w;
#pragma unroll
    for (int o = 8; o > 0; o >>= 1) {
        ps += __shfl_xor_sync(0xffffffffu, ps, o, 16);
        pd += __shfl_xor_sync(0xffffffffu, pd, o, 16);
    }
    if ((tid & 15) == 0) {
        g_als[n * HH + head] = ps;
        g_ald[n * HH + head] = pd;
    }
}

// ---------------- aggregation v2 (fused softmax denominator) ---------------
// 2 nodes per 128-thr block; 64 threads/node, 8 channels (uint4 bf16) each.
// Lane-parallel exp: within each 8-lane head segment, lane i computes the
// exp for edge i of the unroll-8 batch, broadcast via shfl (one exp per
// (edge, head) — 16x fewer MUFU ops than v1). Output always bf16 -> g_a16.
__global__ void agg_kernel(const float* __restrict__ bias) {
    int tid = threadIdx.x;          // 0..127
    int n = blockIdx.x * 2 + (tid >> 6);
    int t = tid & 63;
    int lane = tid & 31;
    int head = t >> 3;              // 8 threads per head
    int li = t & 7;                 // lane-in-segment
    int myc = t * 8;                // 8 channels
    float ald_n = g_ald[n * HH + head];
    float als_n = g_als[n * HH + head];

    // self loop
    float w = __expf(lrelu(als_n + ald_n));
    float acc[8], hv[8];
    cvt8(*(const uint4*)(g_h16 + (size_t)n * HC + myc), hv);
#pragma unroll
    for (int i = 0; i < 8; i++) acc[i] = w * hv[i];
    float wsum = w;

    int beg = g_rowptr[n], end = g_rowptr[n + 1];
    int j = beg;
    for (; j + 8 <= end; j += 8) {
        int s[8];
#pragma unroll
        for (int i = 0; i < 8; i++) s[i] = g_csrc[j + i];
        // my segment-assigned edge's weight
        float wm = __expf(lrelu(g_als[s[li] * HH + head] + ald_n));
        float we[8];
#pragma unroll
        for (int i = 0; i < 8; i++)
            we[i] = __shfl_sync(0xffffffffu, wm, (lane & 24) | i, 32);
#pragma unroll
        for (int i = 0; i < 8; i++) {
            float hs[8];
            cvt8(*(const uint4*)(g_h16 + (size_t)s[i] * HC + myc), hs);
#pragma unroll
            for (int c = 0; c < 8; c++) acc[c] += we[i] * hs[c];
            wsum += we[i];
        }
    }
    for (; j < end; j++) {
        int s = g_csrc[j];
        float we = __expf(lrelu(g_als[s * HH + head] + ald_n));
        float hs[8];
        cvt8(*(const uint4*)(g_h16 + (size_t)s * HC + myc), hs);
#pragma unroll
        for (int c = 0; c < 8; c++) acc[c] += we * hs[c];
        wsum += we;
    }

    float inv = 1.f / wsum;
    float4 b0 = *(const float4*)(bias + myc);
    float4 b1 = *(const float4*)(bias + myc + 4);
    float o[8];
    o[0] = elu1(acc[0] * inv + b0.x); o[1] = elu1(acc[1] * inv + b0.y);
    o[2] = elu1(acc[2] * inv + b0.z); o[3] = elu1(acc[3] * inv + b0.w);
    o[4] = elu1(acc[4] * inv + b1.x); o[5] = elu1(acc[5] * inv + b1.y);
    o[6] = elu1(acc[6] * inv + b1.z); o[7] = elu1(acc[7] * inv + b1.w);
    st_bf16x4(g_a16 + (size_t)n * HC + myc,     make_float4(o[0], o[1], o[2], o[3]));
    st_bf16x4(g_a16 + (size_t)n * HC + myc + 4, make_float4(o[4], o[5], o[6], o[7]));
}

// ---------------- bf16 mma.sync GEMM: h2 = bf16(x1) @ (Whi + Wlo) ----------
// Register double-buffered mainloop. Epilogue: bf16 h2 -> g_h16, and the
// layer-2 attention logits computed DIRECTLY from fp32 accumulators (each
// warp's 64-col N-tile is exactly one head) -> g_als/g_ald. No fp32 h2.
#define GST 40
__global__ __launch_bounds__(256) void gemm_mma(const float* __restrict__ a_s,
                                                const float* __restrict__ a_d) {
    __shared__ __nv_bfloat16 As[128 * GST];
    __shared__ __nv_bfloat16 Bh[128 * GST];
    __shared__ __nv_bfloat16 Bl[128 * GST];
    int tid = threadIdx.x;
    int lane = tid & 31;
    int wid = tid >> 5;
    int bm = blockIdx.x * 128;
    int bn = blockIdx.y * 128;
    int wm = (wid & 3) * 32;       // warp M offset in tile
    int wn = (wid >> 2) * 64;      // warp N offset in tile (one head)

    float acc[2][8][4];
#pragma unroll
    for (int i = 0; i < 2; i++)
#pragma unroll
        for (int j = 0; j < 8; j++)
#pragma unroll
            for (int e = 0; e < 4; e++) acc[i][j][e] = 0.f;

    uint32_t as_b = smem_u32(As);
    uint32_t bh_b = smem_u32(Bh);
    uint32_t bl_b = smem_u32(Bl);

    int a_row = (lane & 7) + ((lane >> 3) & 1) * 8;
    int a_ko  = (lane >> 4) * 8;
    int b_row = (lane & 7) + (lane >> 4) * 8;
    int b_ko  = ((lane >> 3) & 1) * 8;

    int row0 = tid >> 2, ks0 = (tid & 3) * 8;
    int c1 = tid + 256;
    int row1 = c1 >> 2, ks1 = (c1 & 3) * 8;
    bool v0 = (bm + row0) < NN, v1 = (bm + row1) < NN;
    const __nv_bfloat16* a0p = g_a16 + (size_t)(bm + row0) * HC + ks0;
    const __nv_bfloat16* a1p = g_a16 + (size_t)(bm + row1) * HC + ks1;
    const __nv_bfloat16* bh0p = g_whi + (size_t)(bn + row0) * HC + ks0;
    const __nv_bfloat16* bh1p = g_whi + (size_t)(bn + row1) * HC + ks1;
    const __nv_bfloat16* bl0p = g_wlo + (size_t)(bn + row0) * HC + ks0;
    const __nv_bfloat16* bl1p = g_wlo + (size_t)(bn + row1) * HC + ks1;

    uint4 pa0, pa1, pb0, pb1, pl0, pl1;
    const uint4 z4 = make_uint4(0u, 0u, 0u, 0u);
    pa0 = v0 ? *(const uint4*)(a0p) : z4;
    pa1 = v1 ? *(const uint4*)(a1p) : z4;
    pb0 = *(const uint4*)(bh0p);  pb1 = *(const uint4*)(bh1p);
    pl0 = *(const uint4*)(bl0p);  pl1 = *(const uint4*)(bl1p);

    for (int kc = 0; kc < 512; kc += 32) {
        *(uint4*)(As + row0 * GST + ks0) = pa0;
        *(uint4*)(As + row1 * GST + ks1) = pa1;
        *(uint4*)(Bh + row0 * GST + ks0) = pb0;
        *(uint4*)(Bh + row1 * GST + ks1) = pb1;
        *(uint4*)(Bl + row0 * GST + ks0) = pl0;
        *(uint4*)(Bl + row1 * GST + ks1) = pl1;
        __syncthreads();
        if (kc + 32 < 512) {
            int nk = kc + 32;
            pa0 = v0 ? *(const uint4*)(a0p + nk) : z4;
            pa1 = v1 ? *(const uint4*)(a1p + nk) : z4;
            pb0 = *(const uint4*)(bh0p + nk);  pb1 = *(const uint4*)(bh1p + nk);
            pl0 = *(const uint4*)(bl0p + nk);  pl1 = *(const uint4*)(bl1p + nk);
        }

#pragma unroll
        for (int k16 = 0; k16 < 32; k16 += 16) {
            uint32_t a[2][4];
#pragma unroll
            for (int mf = 0; mf < 2; mf++) {
                uint32_t addr = as_b + ((wm + mf * 16 + a_row) * GST + k16 + a_ko) * 2;
                asm volatile("ldmatrix.sync.aligned.m8n8.x4.shared.b16 {%0,%1,%2,%3}, [%4];"
                    : "=r"(a[mf][0]), "=r"(a[mf][1]), "=r"(a[mf][2]), "=r"(a[mf][3])
                    : "r"(addr));
            }
#pragma unroll
            for (int half = 0; half < 2; half++) {
                uint32_t bb = half ? bl_b : bh_b;
                uint32_t bfr[4][4];
#pragma unroll
                for (int g = 0; g < 4; g++) {
                    uint32_t addr = bb + ((wn + g * 16 + b_row) * GST + k16 + b_ko) * 2;
                    asm volatile("ldmatrix.sync.aligned.m8n8.x4.shared.b16 {%0,%1,%2,%3}, [%4];"
                        : "=r"(bfr[g][0]), "=r"(bfr[g][1]), "=r"(bfr[g][2]), "=r"(bfr[g][3])
                        : "r"(addr));
                }
#pragma unroll
                for (int mf = 0; mf < 2; mf++)
#pragma unroll
                    for (int nf = 0; nf < 8; nf++) {
                        uint32_t b0 = bfr[nf >> 1][(nf & 1) ? 2 : 0];
                        uint32_t b1 = bfr[nf >> 1][(nf & 1) ? 3 : 1];
                        asm volatile(
                            "mma.sync.aligned.m16n8k16.row.col.f32.bf16.bf16.f32 "
                            "{%0,%1,%2,%3}, {%4,%5,%6,%7}, {%8,%9}, {%0,%1,%2,%3};"
                            : "+f"(acc[mf][nf][0]), "+f"(acc[mf][nf][1]),
                              "+f"(acc[mf][nf][2]), "+f"(acc[mf][nf][3])
                            : "r"(a[mf][0]), "r"(a[mf][1]), "r"(a[mf][2]), "r"(a[mf][3]),
                              "r"(b0), "r"(b1));
                    }
            }
        }
        __syncthreads();
    }

    // ---- epilogue 1: bf16 h2 -> g_h16 ----
    int rbase = bm + wm + (lane >> 2);
    int cbase = bn + wn + (lane & 3) * 2;
#pragma unroll
    for (int mf = 0; mf < 2; mf++) {
#pragma unroll
        for (int nf = 0; nf < 8; nf++) {
            int col = cbase + nf * 8;
            int r0 = rbase + mf * 16;
            int r1 = r0 + 8;
            if (r0 < NN) {
                __nv_bfloat162 pb = __float22bfloat162_rn(
                    make_float2(acc[mf][nf][0], acc[mf][nf][1]));
                *reinterpret_cast<uint32_t*>(g_h16 + (size_t)r0 * HC + col) =
                    *reinterpret_cast<uint32_t*>(&pb);
            }
            if (r1 < NN) {
                __nv_bfloat162 pb = __float22bfloat162_rn(
                    make_float2(acc[mf][nf][2], acc[mf][nf][3]));
                *reinterpret_cast<uint32_t*>(g_h16 + (size_t)r1 * HC + col) =
                    *reinterpret_cast<uint32_t*>(&pb);
            }
        }
    }

    // ---- epilogue 2: fused layer-2 attention logits (exact fp32 accums) ----
    int head = (bn + wn) >> 6;
    float asv[16], adv[16];
#pragma unroll
    for (int nf = 0; nf < 8; nf++) {
        int ch = (lane & 3) * 2 + nf * 8;
        asv[nf * 2]     = a_s[head * CH + ch];
        asv[nf * 2 + 1] = a_s[head * CH + ch + 1];
        adv[nf * 2]     = a_d[head * CH + ch];
        adv[nf * 2 + 1] = a_d[head * CH + ch + 1];
    }
#pragma unroll
    for (int mf = 0; mf < 2; mf++) {
        float ps0 = 0.f, pd0 = 0.f, ps1 = 0.f, pd1 = 0.f;
#pragma unroll
        for (int nf = 0; nf < 8; nf++) {
            ps0 += acc[mf][nf][0] * asv[nf * 2] + acc[mf][nf][1] * asv[nf * 2 + 1];
            pd0 += acc[mf][nf][0] * adv[nf * 2] + acc[mf][nf][1] * adv[nf * 2 + 1];
            ps1 += acc[mf][nf][2] * asv[nf * 2] + acc[mf][nf][3] * asv[nf * 2 + 1];
            pd1 += acc[mf][nf][2] * adv[nf * 2] + acc[mf][nf][3] * adv[nf * 2 + 1];
        }
#pragma unroll
        for (int o = 1; o <= 2; o <<= 1) {
            ps0 += __shfl_xor_sync(0xffffffffu, ps0, o);
            pd0 += __shfl_xor_sync(0xffffffffu, pd0, o);
            ps1 += __shfl_xor_sync(0xffffffffu, ps1, o);
            pd1 += __shfl_xor_sync(0xffffffffu, pd1, o);
        }
        if ((lane & 3) == 0) {
            int r0 = rbase + mf * 16;
            int r1 = r0 + 8;
            if (r0 < NN) { g_als[r0 * HH + head] = ps0; g_ald[r0 * HH + head] = pd0; }
            if (r1 < NN) { g_als[r1 * HH + head] = ps1; g_ald[r1 * HH + head] = pd1; }
        }
    }
}

// ---------------- global mean pool (segmented; batch sorted; bf16 x2) ------
#define PNODES 256
__global__ void pool_kernel(const int* __restrict__ batch) {
    int base = blockIdx.x * PNODES;
    int tid = threadIdx.x;            // 128
    int c4 = tid * 4;
    int endn = base + PNODES; if (endn > NN) endn = NN;
    if (base >= NN) return;

    int cur = -1;
    float4 acc = make_float4(0.f, 0.f, 0.f, 0.f);
    float cnt = 0.f;
    for (int n = base; n < endn; n++) {
        int g = batch[n];
        if (g != cur) {
            if (cur >= 0) {
                atomicAdd(&g_pool[cur * HC + c4 + 0], acc.x);
                atomicAdd(&g_pool[cur * HC + c4 + 1], acc.y);
                atomicAdd(&g_pool[cur * HC + c4 + 2], acc.z);
                atomicAdd(&g_pool[cur * HC + c4 + 3], acc.w);
                if (tid == 0) atomicAdd(&g_pcnt[cur], cnt);
            }
            cur = g;
            acc = make_float4(0.f, 0.f, 0.f, 0.f);
            cnt = 0.f;
        }
        float4 v = ld_bf16x4(g_a16 + (size_t)n * HC + c4);
        acc.x += v.x; acc.y += v.y; acc.z += v.z; acc.w += v.w;
        cnt += 1.f;
    }
    if (cur >= 0) {
        atomicAdd(&g_pool[cur * HC + c4 + 0], acc.x);
        atomicAdd(&g_pool[cur * HC + c4 + 1], acc.y);
        atomicAdd(&g_pool[cur * HC + c4 + 2], acc.z);
        atomicAdd(&g_pool[cur * HC + c4 + 3], acc.w);
        if (tid == 0) atomicAdd(&g_pcnt[cur], cnt);
    }
}

// ---------------- classifier ----------------------------------------------
__global__ void cls_kernel(const float* __restrict__ Wc,
                           const float* __restrict__ bc,
                           float* __restrict__ out) {
    __shared__ float row[HC];
    int g = blockIdx.x;
    int tid = threadIdx.x;
    float inv = 1.f / fmaxf(g_pcnt[g], 1.f);
    for (int i = tid; i < HC; i += blockDim.x) row[i] = g_pool[g * HC + i] * inv;
    __syncthreads();
    if (tid < OUTC) {
        float s = bc[tid];
        for (int k = 0; k < HC; k++) s += row[k] * Wc[k * OUTC + tid];
        out[g * OUTC + tid] = s;
    }
}

// ---------------- launch ---------------------------------------------------
extern "C" void kernel_launch(void* const* d_in, const int* in_sizes, int n_in,
                              void* d_out, int out_size) {
    const float* x    = (const float*)d_in[0];
    const int*   ei   = (const int*)  d_in[1];
    const int*   batch= (const int*)  d_in[2];
    const float* W1   = (const float*)d_in[3];
    const float* a1s  = (const float*)d_in[4];
    const float* a1d  = (const float*)d_in[5];
    const float* b1   = (const float*)d_in[6];
    const float* W2   = (const float*)d_in[7];
    const float* a2s  = (const float*)d_in[8];
    const float* a2d  = (const float*)d_in[9];
    const float* b2   = (const float*)d_in[10];
    const float* Wc   = (const float*)d_in[11];
    const float* bc   = (const float*)d_in[12];
    float* out = (float*)d_out;

    const int gN = (NN + 255) / 256;
    const int gE = (EE + 255) / 256;

    init_kernel<<<gN, 256>>>();
    wsplit_kernel<<<512, 512>>>(W2);                 // W2 -> bf16 hi/lo (transposed)
    // CSR build (shared by both layers)
    count_kernel<<<gE, 256>>>(ei);
    scan1_kernel<<<NB, 1024>>>();
    scan2_kernel<<<1, 128>>>();
    scan3_kernel<<<gN, 256>>>();
    scatter_kernel<<<gE, 256>>>(ei);

    // ---- layer 1 ----
    proj1_al_kernel<<<NN, 128>>>(x, W1, a1s, a1d);   // h1 (bf16) -> g_h16, logits fp32
    agg_kernel<<<NN / 2, 128>>>(b1);                 // gather g_h16 -> x1 (bf16) g_a16

    // ---- layer 2 ----
    {
        dim3 grid((NN + 127) / 128, 4);
        gemm_mma<<<grid, 256>>>(a2s, a2d);           // h2 (bf16) + fused logits
    }
    agg_kernel<<<NN / 2, 128>>>(b2);                 // gather g_h16 -> x2 (bf16) g_a16

    // ---- readout ----
    pool_kernel<<<(NN + PNODES - 1) / PNODES, 128>>>(batch);
    cls_kernel<<<GG, 128>>>(Wc, bc, out);
}

// round 16
// speedup vs baseline: 1.0147x; 1.0147x over previous
#include <cuda_runtime.h>
#include <cuda_bf16.h>
#include <cstdint>

#define NN 100000
#define EE 1600000
#define HH 8
#define CH 64
#define HC 512
#define GG 64
#define OUTC 10
#define NEG 0.2f
#define NB 98   // ceil(NN/1024)

// ---------------- scratch (device globals; no runtime allocation) ----------
// NOTE: only referenced from device code (host-side use binds the host shadow).
__device__ __nv_bfloat16 g_h16[(size_t)NN * HC];   // h features bf16 (agg gather src)
__device__ __nv_bfloat16 g_a16[(size_t)NN * HC];   // x1 bf16 (GEMM A), then x2 bf16
__device__ __nv_bfloat16 g_whi[HC * HC];           // W2^T hi (n-major, k fast)
__device__ __nv_bfloat16 g_wlo[HC * HC];           // W2^T lo residual
__device__ float g_als[NN * HH];
__device__ float g_ald[NN * HH];
__device__ int   g_deg[NN];
__device__ int   g_cnt[NN];
__device__ int   g_rowptr[NN + 1];
__device__ int   g_csrc[EE];
__device__ float g_pool[GG * HC];
__device__ float g_pcnt[GG];
__device__ int   g_bsum[NB];
__device__ int   g_boff[NB];

__device__ __forceinline__ float lrelu(float x) { return x > 0.f ? x : NEG * x; }
__device__ __forceinline__ float elu1(float x)  { return x > 0.f ? x : expm1f(x); }

__device__ __forceinline__ uint32_t smem_u32(const void* p) {
    uint32_t a;
    asm("{ .reg .u64 t; cvta.to.shared.u64 t, %1; cvt.u32.u64 %0, t; }" : "=r"(a) : "l"(p));
    return a;
}

__device__ __forceinline__ float4 ld_bf16x4(const __nv_bfloat16* p) {
    uint2 q = *(const uint2*)p;
    __nv_bfloat162 a = *reinterpret_cast<__nv_bfloat162*>(&q.x);
    __nv_bfloat162 b = *reinterpret_cast<__nv_bfloat162*>(&q.y);
    float2 fa = __bfloat1622float2(a), fb = __bfloat1622float2(b);
    return make_float4(fa.x, fa.y, fb.x, fb.y);
}
__device__ __forceinline__ void st_bf16x4(__nv_bfloat16* p, float4 v) {
    __nv_bfloat162 p0 = __float22bfloat162_rn(make_float2(v.x, v.y));
    __nv_bfloat162 p1 = __float22bfloat162_rn(make_float2(v.z, v.w));
    uint2 pk;
    pk.x = *reinterpret_cast<uint32_t*>(&p0);
    pk.y = *reinterpret_cast<uint32_t*>(&p1);
    *reinterpret_cast<uint2*>(p) = pk;
}
// 8 bf16 -> 8 floats
__device__ __forceinline__ void cvt8(uint4 q, float* f) {
    __nv_bfloat162 b0 = *reinterpret_cast<__nv_bfloat162*>(&q.x);
    __nv_bfloat162 b1 = *reinterpret_cast<__nv_bfloat162*>(&q.y);
    __nv_bfloat162 b2 = *reinterpret_cast<__nv_bfloat162*>(&q.z);
    __nv_bfloat162 b3 = *reinterpret_cast<__nv_bfloat162*>(&q.w);
    float2 f0 = __bfloat1622float2(b0), f1 = __bfloat1622float2(b1);
    float2 f2 = __bfloat1622float2(b2), f3 = __bfloat1622float2(b3);
    f[0] = f0.x; f[1] = f0.y; f[2] = f1.x; f[3] = f1.y;
    f[4] = f2.x; f[5] = f2.y; f[6] = f3.x; f[7] = f3.y;
}

// ---------------- init: zero accumulators --------------------------------
__global__ void init_kernel() {
    int i = blockIdx.x * blockDim.x + threadIdx.x;
    if (i < NN) { g_deg[i] = 0; g_cnt[i] = 0; }
    if (i < GG * HC) g_pool[i] = 0.f;
    if (i < GG) g_pcnt[i] = 0.f;
}

// ---------------- CSR build ------------------------------------------------
__global__ void count_kernel(const int* __restrict__ ei) {
    int e = blockIdx.x * blockDim.x + threadIdx.x;
    if (e >= EE) return;
    atomicAdd(&g_deg[ei[EE + e]], 1);   // dst
}

__global__ void scan1_kernel() {
    __shared__ int sh[1024];
    int tid = threadIdx.x;
    int i = blockIdx.x * 1024 + tid;
    int v = (i < NN) ? g_deg[i] : 0;
    sh[tid] = v;
    __syncthreads();
    for (int off = 1; off < 1024; off <<= 1) {
        int t = (tid >= off) ? sh[tid - off] : 0;
        __syncthreads();
        sh[tid] += t;
        __syncthreads();
    }
    if (i < NN) g_rowptr[i] = sh[tid] - v;
    if (tid == 1023) g_bsum[blockIdx.x] = sh[1023];
}

__global__ void scan2_kernel() {      // one block, parallel scan over NB
    __shared__ int sh[128];
    int tid = threadIdx.x;
    int v = (tid < NB) ? g_bsum[tid] : 0;
    sh[tid] = v;
    __syncthreads();
    for (int off = 1; off < 128; off <<= 1) {
        int t = (tid >= off) ? sh[tid - off] : 0;
        __syncthreads();
        sh[tid] += t;
        __syncthreads();
    }
    if (tid < NB) g_boff[tid] = sh[tid] - v;   // exclusive
}

__global__ void scan3_kernel() {
    int i = blockIdx.x * blockDim.x + threadIdx.x;
    if (i < NN) g_rowptr[i] += g_boff[i >> 10];
    if (i == 0) g_rowptr[NN] = EE;
}

__global__ void scatter_kernel(const int* __restrict__ ei) {
    int e = blockIdx.x * blockDim.x + threadIdx.x;
    if (e >= EE) return;
    int s = ei[e];
    int d = ei[EE + e];
    int pos = g_rowptr[d] + atomicAdd(&g_cnt[d], 1);
    g_csrc[pos] = s;
}

// ---------------- W2 split: hi/lo bf16, transposed (n-major, k fast) -------
__global__ void wsplit_kernel(const float* __restrict__ W2) {
    int idx = blockIdx.x * blockDim.x + threadIdx.x;   // 512*512
    int n = idx >> 9, k = idx & 511;
    float w = W2[k * HC + n];
    __nv_bfloat16 hi = __float2bfloat16(w);
    float lo = w - __bfloat162float(hi);
    g_whi[n * HC + k] = hi;
    g_wlo[n * HC + k] = __float2bfloat16(lo);
}

// ---------------- layer-1 projection (K=3) + attention logits -------------
// logits computed from exact fp32 register values; h1 stored bf16 only.
__global__ void proj1_al_kernel(const float* __restrict__ x,
                                const float* __restrict__ W1,
                                const float* __restrict__ a_s,
                                const float* __restrict__ a_d) {
    int n = blockIdx.x;
    int tid = threadIdx.x;
    float x0 = x[n * 3 + 0], x1 = x[n * 3 + 1], x2 = x[n * 3 + 2];
    int c4 = tid * 4;
    float4 w0 = *(const float4*)(W1 + 0 * HC + c4);
    float4 w1 = *(const float4*)(W1 + 1 * HC + c4);
    float4 w2 = *(const float4*)(W1 + 2 * HC + c4);
    float4 h;
    h.x = x0 * w0.x + x1 * w1.x + x2 * w2.x;
    h.y = x0 * w0.y + x1 * w1.y + x2 * w2.y;
    h.z = x0 * w0.z + x1 * w1.z + x2 * w2.z;
    h.w = x0 * w0.w + x1 * w1.w + x2 * w2.w;
    st_bf16x4(g_h16 + (size_t)n * HC + c4, h);

    int head = tid >> 4;
    int cc = (tid & 15) * 4;
    float4 as4 = *(const float4*)(a_s + head * CH + cc);
    float4 ad4 = *(const float4*)(a_d + head * CH + cc);
    float ps = h.x * as4.x + h.y * as4.y + h.z * as4.z + h.w * as4.w;
    float pd = h.x * ad4.x + h.y * ad4.y + h.z * ad4.z + h.w * ad4.w;
#pragma unroll
    for (int o = 8; o > 0; o >>= 1) {
        ps += __shfl_xor_sync(0xffffffffu, ps, o, 16);
        pd += __shfl_xor_sync(0xffffffffu, pd, o, 16);
    }
    if ((tid & 15) == 0) {
        g_als[n * HH + head] = ps;
        g_ald[n * HH + head] = pd;
    }
}

// ---------------- aggregation v2 (fused softmax denominator) ---------------
// 2 nodes per 128-thr block; 64 threads/node, 8 channels (uint4 bf16) each.
// Lane-parallel exp: within each 8-lane head segment, lane i computes the
// exp for edge i of the unroll-8 batch, broadcast via shfl (one exp per
// (edge, head) — 16x fewer MUFU ops than v1). Output always bf16 -> g_a16.
__global__ void agg_kernel(const float* __restrict__ bias) {
    int tid = threadIdx.x;          // 0..127
    int n = blockIdx.x * 2 + (tid >> 6);
    int t = tid & 63;
    int lane = tid & 31;
    int head = t >> 3;              // 8 threads per head
    int li = t & 7;                 // lane-in-segment
    int myc = t * 8;                // 8 channels
    float ald_n = g_ald[n * HH + head];
    float als_n = g_als[n * HH + head];

    // self loop
    float w = __expf(lrelu(als_n + ald_n));
    float acc[8], hv[8];
    cvt8(*(const uint4*)(g_h16 + (size_t)n * HC + myc), hv);
#pragma unroll
    for (int i = 0; i < 8; i++) acc[i] = w * hv[i];
    float wsum = w;

    int beg = g_rowptr[n], end = g_rowptr[n + 1];
    int j = beg;
    for (; j + 8 <= end; j += 8) {
        int s[8];
#pragma unroll
        for (int i = 0; i < 8; i++) s[i] = g_csrc[j + i];
        // my segment-assigned edge's weight
        float wm = __expf(lrelu(g_als[s[li] * HH + head] + ald_n));
        float we[8];
#pragma unroll
        for (int i = 0; i < 8; i++)
            we[i] = __shfl_sync(0xffffffffu, wm, (lane & 24) | i, 32);
#pragma unroll
        for (int i = 0; i < 8; i++) {
            float hs[8];
            cvt8(*(const uint4*)(g_h16 + (size_t)s[i] * HC + myc), hs);
#pragma unroll
            for (int c = 0; c < 8; c++) acc[c] += we[i] * hs[c];
            wsum += we[i];
        }
    }
    for (; j < end; j++) {
        int s = g_csrc[j];
        float we = __expf(lrelu(g_als[s * HH + head] + ald_n));
        float hs[8];
        cvt8(*(const uint4*)(g_h16 + (size_t)s * HC + myc), hs);
#pragma unroll
        for (int c = 0; c < 8; c++) acc[c] += we * hs[c];
        wsum += we;
    }

    float inv = 1.f / wsum;
    float4 b0 = *(const float4*)(bias + myc);
    float4 b1 = *(const float4*)(bias + myc + 4);
    float o[8];
    o[0] = elu1(acc[0] * inv + b0.x); o[1] = elu1(acc[1] * inv + b0.y);
    o[2] = elu1(acc[2] * inv + b0.z); o[3] = elu1(acc[3] * inv + b0.w);
    o[4] = elu1(acc[4] * inv + b1.x); o[5] = elu1(acc[5] * inv + b1.y);
    o[6] = elu1(acc[6] * inv + b1.z); o[7] = elu1(acc[7] * inv + b1.w);
    st_bf16x4(g_a16 + (size_t)n * HC + myc,     make_float4(o[0], o[1], o[2], o[3]));
    st_bf16x4(g_a16 + (size_t)n * HC + myc + 4, make_float4(o[4], o[5], o[6], o[7]));
}

// ---------------- bf16 mma.sync GEMM: h2 = bf16(x1) @ (Whi + Wlo) ----------
// Register double-buffered mainloop. Epilogue: bf16 h2 -> g_h16, and the
// layer-2 attention logits computed DIRECTLY from fp32 accumulators (each
// warp's 64-col N-tile is exactly one head) -> g_als/g_ald. No fp32 h2.
#define GST 40
__global__ __launch_bounds__(256) void gemm_mma(const float* __restrict__ a_s,
                                                const float* __restrict__ a_d) {
    __shared__ __nv_bfloat16 As[128 * GST];
    __shared__ __nv_bfloat16 Bh[128 * GST];
    __shared__ __nv_bfloat16 Bl[128 * GST];
    int tid = threadIdx.x;
    int lane = tid & 31;
    int wid = tid >> 5;
    int bm = blockIdx.x * 128;
    int bn = blockIdx.y * 128;
    int wm = (wid & 3) * 32;       // warp M offset in tile
    int wn = (wid >> 2) * 64;      // warp N offset in tile (one head)

    float acc[2][8][4];
#pragma unroll
    for (int i = 0; i < 2; i++)
#pragma unroll
        for (int j = 0; j < 8; j++)
#pragma unroll
            for (int e = 0; e < 4; e++) acc[i][j][e] = 0.f;

    uint32_t as_b = smem_u32(As);
    uint32_t bh_b = smem_u32(Bh);
    uint32_t bl_b = smem_u32(Bl);

    int a_row = (lane & 7) + ((lane >> 3) & 1) * 8;
    int a_ko  = (lane >> 4) * 8;
    int b_row = (lane & 7) + (lane >> 4) * 8;
    int b_ko  = ((lane >> 3) & 1) * 8;

    int row0 = tid >> 2, ks0 = (tid & 3) * 8;
    int c1 = tid + 256;
    int row1 = c1 >> 2, ks1 = (c1 & 3) * 8;
    bool v0 = (bm + row0) < NN, v1 = (bm + row1) < NN;
    const __nv_bfloat16* a0p = g_a16 + (size_t)(bm + row0) * HC + ks0;
    const __nv_bfloat16* a1p = g_a16 + (size_t)(bm + row1) * HC + ks1;
    const __nv_bfloat16* bh0p = g_whi + (size_t)(bn + row0) * HC + ks0;
    const __nv_bfloat16* bh1p = g_whi + (size_t)(bn + row1) * HC + ks1;
    const __nv_bfloat16* bl0p = g_wlo + (size_t)(bn + row0) * HC + ks0;
    const __nv_bfloat16* bl1p = g_wlo + (size_t)(bn + row1) * HC + ks1;

    uint4 pa0, pa1, pb0, pb1, pl0, pl1;
    const uint4 z4 = make_uint4(0u, 0u, 0u, 0u);
    pa0 = v0 ? *(const uint4*)(a0p) : z4;
    pa1 = v1 ? *(const uint4*)(a1p) : z4;
    pb0 = *(const uint4*)(bh0p);  pb1 = *(const uint4*)(bh1p);
    pl0 = *(const uint4*)(bl0p);  pl1 = *(const uint4*)(bl1p);

    for (int kc = 0; kc < 512; kc += 32) {
        *(uint4*)(As + row0 * GST + ks0) = pa0;
        *(uint4*)(As + row1 * GST + ks1) = pa1;
        *(uint4*)(Bh + row0 * GST + ks0) = pb0;
        *(uint4*)(Bh + row1 * GST + ks1) = pb1;
        *(uint4*)(Bl + row0 * GST + ks0) = pl0;
        *(uint4*)(Bl + row1 * GST + ks1) = pl1;
        __syncthreads();
        if (kc + 32 < 512) {
            int nk = kc + 32;
            pa0 = v0 ? *(const uint4*)(a0p + nk) : z4;
            pa1 = v1 ? *(const uint4*)(a1p + nk) : z4;
            pb0 = *(const uint4*)(bh0p + nk);  pb1 = *(const uint4*)(bh1p + nk);
            pl0 = *(const uint4*)(bl0p + nk);  pl1 = *(const uint4*)(bl1p + nk);
        }

#pragma unroll
        for (int k16 = 0; k16 < 32; k16 += 16) {
            uint32_t a[2][4];
#pragma unroll
            for (int mf = 0; mf < 2; mf++) {
                uint32_t addr = as_b + ((wm + mf * 16 + a_row) * GST + k16 + a_ko) * 2;
                asm volatile("ldmatrix.sync.aligned.m8n8.x4.shared.b16 {%0,%1,%2,%3}, [%4];"
                    : "=r"(a[mf][0]), "=r"(a[mf][1]), "=r"(a[mf][2]), "=r"(a[mf][3])
                    : "r"(addr));
            }
#pragma unroll
            for (int half = 0; half < 2; half++) {
                uint32_t bb = half ? bl_b : bh_b;
                uint32_t bfr[4][4];
#pragma unroll
                for (int g = 0; g < 4; g++) {
                    uint32_t addr = bb + ((wn + g * 16 + b_row) * GST + k16 + b_ko) * 2;
                    asm volatile("ldmatrix.sync.aligned.m8n8.x4.shared.b16 {%0,%1,%2,%3}, [%4];"
                        : "=r"(bfr[g][0]), "=r"(bfr[g][1]), "=r"(bfr[g][2]), "=r"(bfr[g][3])
                        : "r"(addr));
                }
#pragma unroll
                for (int mf = 0; mf < 2; mf++)
#pragma unroll
                    for (int nf = 0; nf < 8; nf++) {
                        uint32_t b0 = bfr[nf >> 1][(nf & 1) ? 2 : 0];
                        uint32_t b1 = bfr[nf >> 1][(nf & 1) ? 3 : 1];
                        asm volatile(
                            "mma.sync.aligned.m16n8k16.row.col.f32.bf16.bf16.f32 "
                            "{%0,%1,%2,%3}, {%4,%5,%6,%7}, {%8,%9}, {%0,%1,%2,%3};"
                            : "+f"(acc[mf][nf][0]), "+f"(acc[mf][nf][1]),
                              "+f"(acc[mf][nf][2]), "+f"(acc[mf][nf][3])
                            : "r"(a[mf][0]), "r"(a[mf][1]), "r"(a[mf][2]), "r"(a[mf][3]),
                              "r"(b0), "r"(b1));
                    }
            }
        }
        __syncthreads();
    }

    // ---- epilogue 1: bf16 h2 -> g_h16 ----
    int rbase = bm + wm + (lane >> 2);
    int cbase = bn + wn + (lane & 3) * 2;
#pragma unroll
    for (int mf = 0; mf < 2; mf++) {
#pragma unroll
        for (int nf = 0; nf < 8; nf++) {
            int col = cbase + nf * 8;
            int r0 = rbase + mf * 16;
            int r1 = r0 + 8;
            if (r0 < NN) {
                __nv_bfloat162 pb = __float22bfloat162_rn(
                    make_float2(acc[mf][nf][0], acc[mf][nf][1]));
                *reinterpret_cast<uint32_t*>(g_h16 + (size_t)r0 * HC + col) =
                    *reinterpret_cast<uint32_t*>(&pb);
            }
            if (r1 < NN) {
                __nv_bfloat162 pb = __float22bfloat162_rn(
                    make_float2(acc[mf][nf][2], acc[mf][nf][3]));
                *reinterpret_cast<uint32_t*>(g_h16 + (size_t)r1 * HC + col) =
                    *reinterpret_cast<uint32_t*>(&pb);
            }
        }
    }

    // ---- epilogue 2: fused layer-2 attention logits (exact fp32 accums) ----
    int head = (bn + wn) >> 6;
    float asv[16], adv[16];
#pragma unroll
    for (int nf = 0; nf < 8; nf++) {
        int ch = (lane & 3) * 2 + nf * 8;
        asv[nf * 2]     = a_s[head * CH + ch];
        asv[nf * 2 + 1] = a_s[head * CH + ch + 1];
        adv[nf * 2]     = a_d[head * CH + ch];
        adv[nf * 2 + 1] = a_d[head * CH + ch + 1];
    }
#pragma unroll
    for (int mf = 0; mf < 2; mf++) {
        float ps0 = 0.f, pd0 = 0.f, ps1 = 0.f, pd1 = 0.f;
#pragma unroll
        for (int nf = 0; nf < 8; nf++) {
            ps0 += acc[mf][nf][0] * asv[nf * 2] + acc[mf][nf][1] * asv[nf * 2 + 1];
            pd0 += acc[mf][nf][0] * adv[nf * 2] + acc[mf][nf][1] * adv[nf * 2 + 1];
            ps1 += acc[mf][nf][2] * asv[nf * 2] + acc[mf][nf][3] * asv[nf * 2 + 1];
            pd1 += acc[mf][nf][2] * adv[nf * 2] + acc[mf][nf][3] * adv[nf * 2 + 1];
        }
#pragma unroll
        for (int o = 1; o <= 2; o <<= 1) {
            ps0 += __shfl_xor_sync(0xffffffffu, ps0, o);
            pd0 += __shfl_xor_sync(0xffffffffu, pd0, o);
            ps1 += __shfl_xor_sync(0xffffffffu, ps1, o);
            pd1 += __shfl_xor_sync(0xffffffffu, pd1, o);
        }
        if ((lane & 3) == 0) {
            int r0 = rbase + mf * 16;
            int r1 = r0 + 8;
            if (r0 < NN) { g_als[r0 * HH + head] = ps0; g_ald[r0 * HH + head] = pd0; }
            if (r1 < NN) { g_als[r1 * HH + head] = ps1; g_ald[r1 * HH + head] = pd1; }
        }
    }
}

// ---------------- global mean pool (segmented; batch sorted; bf16 x2) ------
#define PNODES 256
__global__ void pool_kernel(const int* __restrict__ batch) {
    int base = blockIdx.x * PNODES;
    int tid = threadIdx.x;            // 128
    int c4 = tid * 4;
    int endn = base + PNODES; if (endn > NN) endn = NN;
    if (base >= NN) return;

    int cur = -1;
    float4 acc = make_float4(0.f, 0.f, 0.f, 0.f);
    float cnt = 0.f;
    for (int n = base; n < endn; n++) {
        int g = batch[n];
        if (g != cur) {
            if (cur >= 0) {
                atomicAdd(&g_pool[cur * HC + c4 + 0], acc.x);
                atomicAdd(&g_pool[cur * HC + c4 + 1], acc.y);
                atomicAdd(&g_pool[cur * HC + c4 + 2], acc.z);
                atomicAdd(&g_pool[cur * HC + c4 + 3], acc.w);
                if (tid == 0) atomicAdd(&g_pcnt[cur], cnt);
            }
            cur = g;
            acc = make_float4(0.f, 0.f, 0.f, 0.f);
            cnt = 0.f;
        }
        float4 v = ld_bf16x4(g_a16 + (size_t)n * HC + c4);
        acc.x += v.x; acc.y += v.y; acc.z += v.z; acc.w += v.w;
        cnt += 1.f;
    }
    if (cur >= 0) {
        atomicAdd(&g_pool[cur * HC + c4 + 0], acc.x);
        atomicAdd(&g_pool[cur * HC + c4 + 1], acc.y);
        atomicAdd(&g_pool[cur * HC + c4 + 2], acc.z);
        atomicAdd(&g_pool[cur * HC + c4 + 3], acc.w);
        if (tid == 0) atomicAdd(&g_pcnt[cur], cnt);
    }
}

// ---------------- classifier ----------------------------------------------
__global__ void cls_kernel(const float* __restrict__ Wc,
                           const float* __restrict__ bc,
                           float* __restrict__ out) {
    __shared__ float row[HC];
    int g = blockIdx.x;
    int tid = threadIdx.x;
    float inv = 1.f / fmaxf(g_pcnt[g], 1.f);
    for (int i = tid; i < HC; i += blockDim.x) row[i] = g_pool[g * HC + i] * inv;
    __syncthreads();
    if (tid < OUTC) {
        float s = bc[tid];
        for (int k = 0; k < HC; k++) s += row[k] * Wc[k * OUTC + tid];
        out[g * OUTC + tid] = s;
    }
}

// ---------------- launch ---------------------------------------------------
extern "C" void kernel_launch(void* const* d_in, const int* in_sizes, int n_in,
                              void* d_out, int out_size) {
    const float* x    = (const float*)d_in[0];
    const int*   ei   = (const int*)  d_in[1];
    const int*   batch= (const int*)  d_in[2];
    const float* W1   = (const float*)d_in[3];
    const float* a1s  = (const float*)d_in[4];
    const float* a1d  = (const float*)d_in[5];
    const float* b1   = (const float*)d_in[6];
    const float* W2   = (const float*)d_in[7];
    const float* a2s  = (const float*)d_in[8];
    const float* a2d  = (const float*)d_in[9];
    const float* b2   = (const float*)d_in[10];
    const float* Wc   = (const float*)d_in[11];
    const float* bc   = (const float*)d_in[12];
    float* out = (float*)d_out;

    const int gN = (NN + 255) / 256;
    const int gE = (EE + 255) / 256;

    init_kernel<<<gN, 256>>>();
    wsplit_kernel<<<512, 512>>>(W2);                 // W2 -> bf16 hi/lo (transposed)
    // CSR build (shared by both layers)
    count_kernel<<<gE, 256>>>(ei);
    scan1_kernel<<<NB, 1024>>>();
    scan2_kernel<<<1, 128>>>();
    scan3_kernel<<<gN, 256>>>();
    scatter_kernel<<<gE, 256>>>(ei);

    // ---- layer 1 ----
    proj1_al_kernel<<<NN, 128>>>(x, W1, a1s, a1d);   // h1 (bf16) -> g_h16, logits fp32
    agg_kernel<<<NN / 2, 128>>>(b1);                 // gather g_h16 -> x1 (bf16) g_a16

    // ---- layer 2 ----
    {
        dim3 grid((NN + 127) / 128, 4);
        gemm_mma<<<grid, 256>>>(a2s, a2d);           // h2 (bf16) + fused logits
    }
    agg_kernel<<<NN / 2, 128>>>(b2);                 // gather g_h16 -> x2 (bf16) g_a16

    // ---- readout ----
    pool_kernel<<<(NN + PNODES - 1) / PNODES, 128>>>(batch);
    cls_kernel<<<GG, 128>>>(Wc, bc, out);
}